// round 1
// baseline (speedup 1.0000x reference)
#include <cuda_runtime.h>
#include <math.h>

// Problem constants
#define Bc 4
#define Hc 12
#define Sc 2048
#define Dc 64

// Tiling
#define TQ 64
#define TK 64
#define NT 256
#define LST 68          // padded smem row stride in floats (17 float4)
#define SMEM_BYTES (4 * 64 * LST * 4 + 2 * 64 * 4)

__global__ __launch_bounds__(NT, 2)
void attn_fused_kernel(const float* __restrict__ Q, const float* __restrict__ K,
                       const float* __restrict__ V, const int* __restrict__ mask,
                       float* __restrict__ Out, float* __restrict__ P)
{
    extern __shared__ float sm[];
    float* Qs = sm;                    // 64 x LST
    float* Ks = Qs + 64 * LST;         // 64 x LST
    float* Vs = Ks + 64 * LST;         // 64 x LST
    float* Ps = Vs + 64 * LST;         // 64 x LST
    int*   mq = (int*)(Ps + 64 * LST); // 64
    int*   mk = mq + 64;               // 64

    const int t  = threadIdx.x;
    const int bh = blockIdx.y;
    const int b  = bh / Hc;
    const int q0 = blockIdx.x * TQ;
    const int tr = t >> 4;     // 0..15 row group
    const int tc = t & 15;     // 0..15 col group
    const int r0 = tr * 4;
    const int c0 = tc * 4;

    const float* Qbh = Q + (size_t)bh * Sc * Dc;
    const float* Kbh = K + (size_t)bh * Sc * Dc;
    const float* Vbh = V + (size_t)bh * Sc * Dc;

    // ---- Load Q tile (contiguous 64x64 floats) into padded smem ----
    {
        const float4* g  = (const float4*)(Qbh + (size_t)q0 * Dc);
        float4*       s4 = (float4*)Qs;
        #pragma unroll
        for (int i = t; i < 1024; i += NT)
            s4[(i >> 4) * 17 + (i & 15)] = g[i];
        if (t < 64) mq[t] = mask[b * Sc + q0 + t];
    }
    __syncthreads();

    int mqr[4];
    #pragma unroll
    for (int i = 0; i < 4; i++) mqr[i] = mq[r0 + i];

    float m_i[4], l_i[4];
    #pragma unroll
    for (int i = 0; i < 4; i++) { m_i[i] = -INFINITY; l_i[i] = 0.f; }

    // =======================  PASS 1: softmax stats  =======================
    for (int kt = 0; kt < Sc; kt += TK) {
        {
            const float4* g  = (const float4*)(Kbh + (size_t)kt * Dc);
            float4*       s4 = (float4*)Ks;
            #pragma unroll
            for (int i = t; i < 1024; i += NT)
                s4[(i >> 4) * 17 + (i & 15)] = g[i];
            if (t < 64) mk[t] = mask[b * Sc + kt + t];
        }
        __syncthreads();

        float acc[4][4];
        #pragma unroll
        for (int i = 0; i < 4; i++)
            #pragma unroll
            for (int j = 0; j < 4; j++) acc[i][j] = 0.f;

        const float4* q4 = (const float4*)Qs;
        const float4* k4 = (const float4*)Ks;
        #pragma unroll
        for (int d4 = 0; d4 < 16; d4++) {
            float4 qv[4], kv[4];
            #pragma unroll
            for (int i = 0; i < 4; i++) qv[i] = q4[(r0 + i) * 17 + d4];
            #pragma unroll
            for (int j = 0; j < 4; j++) kv[j] = k4[(c0 + j) * 17 + d4];
            #pragma unroll
            for (int i = 0; i < 4; i++)
                #pragma unroll
                for (int j = 0; j < 4; j++)
                    acc[i][j] += qv[i].x * kv[j].x + qv[i].y * kv[j].y +
                                 qv[i].z * kv[j].z + qv[i].w * kv[j].w;
        }

        int mkc[4];
        #pragma unroll
        for (int j = 0; j < 4; j++) mkc[j] = mk[c0 + j];

        #pragma unroll
        for (int i = 0; i < 4; i++) {
            float s[4];
            #pragma unroll
            for (int j = 0; j < 4; j++)
                s[j] = (mqr[i] && mkc[j]) ? acc[i][j] * 0.125f : -1e9f;
            float tm = fmaxf(fmaxf(s[0], s[1]), fmaxf(s[2], s[3]));
            float nm = fmaxf(m_i[i], tm);
            float add = __expf(s[0] - nm) + __expf(s[1] - nm) +
                        __expf(s[2] - nm) + __expf(s[3] - nm);
            l_i[i] = l_i[i] * __expf(m_i[i] - nm) + add;
            m_i[i] = nm;
        }
        __syncthreads();
    }

    // butterfly combine across the 16 lanes of a row group
    #pragma unroll
    for (int off = 1; off < 16; off <<= 1) {
        #pragma unroll
        for (int i = 0; i < 4; i++) {
            float om = __shfl_xor_sync(0xffffffffu, m_i[i], off, 16);
            float ol = __shfl_xor_sync(0xffffffffu, l_i[i], off, 16);
            float nm = fmaxf(m_i[i], om);
            l_i[i] = l_i[i] * __expf(m_i[i] - nm) + ol * __expf(om - nm);
            m_i[i] = nm;
        }
    }
    float linv[4];
    #pragma unroll
    for (int i = 0; i < 4; i++) linv[i] = 1.f / l_i[i];

    // =======================  PASS 2: P write + P@V  =======================
    float oacc[4][4];
    #pragma unroll
    for (int i = 0; i < 4; i++)
        #pragma unroll
        for (int j = 0; j < 4; j++) oacc[i][j] = 0.f;

    for (int kt = 0; kt < Sc; kt += TK) {
        {
            const float4* gk = (const float4*)(Kbh + (size_t)kt * Dc);
            const float4* gv = (const float4*)(Vbh + (size_t)kt * Dc);
            float4* sk = (float4*)Ks;
            float4* sv = (float4*)Vs;
            #pragma unroll
            for (int i = t; i < 1024; i += NT) {
                int idx = (i >> 4) * 17 + (i & 15);
                sk[idx] = gk[i];
                sv[idx] = gv[i];
            }
            if (t < 64) mk[t] = mask[b * Sc + kt + t];
        }
        __syncthreads();

        float acc[4][4];
        #pragma unroll
        for (int i = 0; i < 4; i++)
            #pragma unroll
            for (int j = 0; j < 4; j++) acc[i][j] = 0.f;

        const float4* q4 = (const float4*)Qs;
        const float4* k4 = (const float4*)Ks;
        #pragma unroll
        for (int d4 = 0; d4 < 16; d4++) {
            float4 qv[4], kv[4];
            #pragma unroll
            for (int i = 0; i < 4; i++) qv[i] = q4[(r0 + i) * 17 + d4];
            #pragma unroll
            for (int j = 0; j < 4; j++) kv[j] = k4[(c0 + j) * 17 + d4];
            #pragma unroll
            for (int i = 0; i < 4; i++)
                #pragma unroll
                for (int j = 0; j < 4; j++)
                    acc[i][j] += qv[i].x * kv[j].x + qv[i].y * kv[j].y +
                                 qv[i].z * kv[j].z + qv[i].w * kv[j].w;
        }

        int mkc[4];
        #pragma unroll
        for (int j = 0; j < 4; j++) mkc[j] = mk[c0 + j];

        #pragma unroll
        for (int i = 0; i < 4; i++) {
            float4 pv;
            float s0 = (mqr[i] && mkc[0]) ? acc[i][0] * 0.125f : -1e9f;
            float s1 = (mqr[i] && mkc[1]) ? acc[i][1] * 0.125f : -1e9f;
            float s2 = (mqr[i] && mkc[2]) ? acc[i][2] * 0.125f : -1e9f;
            float s3 = (mqr[i] && mkc[3]) ? acc[i][3] * 0.125f : -1e9f;
            pv.x = __expf(s0 - m_i[i]) * linv[i];
            pv.y = __expf(s1 - m_i[i]) * linv[i];
            pv.z = __expf(s2 - m_i[i]) * linv[i];
            pv.w = __expf(s3 - m_i[i]) * linv[i];
            ((float4*)Ps)[(r0 + i) * 17 + tc] = pv;
            *(float4*)(P + ((size_t)bh * Sc + (size_t)(q0 + r0 + i)) * Sc + kt + c0) = pv;
        }
        __syncthreads();

        // P(tile) @ V(tile) with 4x4 register tiling
        const float4* v4 = (const float4*)Vs;
        #pragma unroll 8
        for (int col = 0; col < 64; col++) {
            float4 vv = v4[col * 17 + tc];
            #pragma unroll
            for (int i = 0; i < 4; i++) {
                float pr = Ps[(r0 + i) * LST + col];
                oacc[i][0] += pr * vv.x;
                oacc[i][1] += pr * vv.y;
                oacc[i][2] += pr * vv.z;
                oacc[i][3] += pr * vv.w;
            }
        }
        __syncthreads();
    }

    // ---- write O ----
    #pragma unroll
    for (int i = 0; i < 4; i++) {
        float4 o = make_float4(oacc[i][0], oacc[i][1], oacc[i][2], oacc[i][3]);
        *(float4*)(Out + ((size_t)bh * Sc + (size_t)(q0 + r0 + i)) * Dc + c0) = o;
    }
}

extern "C" void kernel_launch(void* const* d_in, const int* in_sizes, int n_in,
                              void* d_out, int out_size)
{
    const float* Q    = (const float*)d_in[0];
    const float* K    = (const float*)d_in[1];
    const float* V    = (const float*)d_in[2];
    const int*   mask = (const int*)d_in[3];
    // output = concat(out [B,H,S,D], p_attn [B,H,S,S])
    float* out = (float*)d_out;
    float* P   = out + (size_t)Bc * Hc * Sc * Dc;

    cudaFuncSetAttribute(attn_fused_kernel,
                         cudaFuncAttributeMaxDynamicSharedMemorySize, SMEM_BYTES);

    dim3 grid(Sc / TQ, Bc * Hc);
    attn_fused_kernel<<<grid, NT, SMEM_BYTES>>>(Q, K, V, mask, out, P);
}

// round 5
// speedup vs baseline: 1.9293x; 1.9293x over previous
#include <cuda_runtime.h>
#include <math.h>

// Problem constants
#define Bc 4
#define Hc 12
#define Sc 2048
#define Dc 64

// Tiling: 128 q-rows x 64 k-cols per block, 256 threads, 8x4 per thread
#define TQ 128
#define TK 64
#define NT 256
#define QST 68   // padded row stride (floats) = 17 float4
#define SMEM_BYTES ((TQ*QST + TK*QST + TK*QST + TQ*QST) * 4 + (TQ + TK) * 4)

// per-row 1/l for the P-normalize pass
__device__ float g_linv[Bc * Hc * Sc];

__global__ __launch_bounds__(NT, 2)
void attn_main_kernel(const float* __restrict__ Q, const float* __restrict__ K,
                      const float* __restrict__ V, const int* __restrict__ mask,
                      float* __restrict__ Out, float* __restrict__ P)
{
    extern __shared__ float sm[];
    float* Qs = sm;                  // TQ x QST
    float* Ks = Qs + TQ * QST;       // TK x QST
    float* Vs = Ks + TK * QST;       // TK x QST
    float* Ps = Vs + TK * QST;       // TQ x QST (64 cols used)
    int*   mq = (int*)(Ps + TQ * QST); // TQ
    int*   mk = mq + TQ;               // TK

    const int t  = threadIdx.x;
    const int bh = blockIdx.y;
    const int b  = bh / Hc;
    const int q0 = blockIdx.x * TQ;
    const int tr = t >> 4;      // 0..15
    const int tc = t & 15;      // 0..15
    const int r0 = tr * 8;      // 8 q-rows per thread
    const int c0 = tc * 4;      // 4 k-cols per thread

    const float* Qbh = Q + (size_t)bh * Sc * Dc;
    const float* Kbh = K + (size_t)bh * Sc * Dc;
    const float* Vbh = V + (size_t)bh * Sc * Dc;

    // ---- Load Q tile: 128x64 floats = 2048 float4 ----
    {
        const float4* g  = (const float4*)(Qbh + (size_t)q0 * Dc);
        float4*       s4 = (float4*)Qs;
        #pragma unroll
        for (int i = t; i < TQ * 16; i += NT)
            s4[(i >> 4) * 17 + (i & 15)] = g[i];
        if (t < TQ) mq[t] = mask[b * Sc + q0 + t];
    }
    __syncthreads();

    int mqr[8];
    #pragma unroll
    for (int i = 0; i < 8; i++) mqr[i] = mq[r0 + i];

    float l_i[8];
    float oacc[8][4];
    #pragma unroll
    for (int i = 0; i < 8; i++) {
        l_i[i] = 0.f;
        #pragma unroll
        for (int j = 0; j < 4; j++) oacc[i][j] = 0.f;
    }

    const float4* q4 = (const float4*)Qs;
    const float4* k4 = (const float4*)Ks;
    const float4* v4 = (const float4*)Vs;

    for (int kt = 0; kt < Sc; kt += TK) {
        // ---- load K,V tiles (64x64 each = 1024 float4) ----
        {
            const float4* gk = (const float4*)(Kbh + (size_t)kt * Dc);
            const float4* gv = (const float4*)(Vbh + (size_t)kt * Dc);
            float4* sk = (float4*)Ks;
            float4* sv = (float4*)Vs;
            #pragma unroll
            for (int i = t; i < TK * 16; i += NT) {
                int idx = (i >> 4) * 17 + (i & 15);
                sk[idx] = gk[i];
                sv[idx] = gv[i];
            }
            if (t < TK) mk[t] = mask[b * Sc + kt + t];
        }
        __syncthreads();

        // ---- QK^T: acc[8][4] ----
        float acc[8][4];
        #pragma unroll
        for (int i = 0; i < 8; i++)
            #pragma unroll
            for (int j = 0; j < 4; j++) acc[i][j] = 0.f;

        #pragma unroll 4
        for (int d4 = 0; d4 < 16; d4++) {
            float4 kv[4];
            #pragma unroll
            for (int j = 0; j < 4; j++) kv[j] = k4[(c0 + j) * 17 + d4];
            #pragma unroll
            for (int i = 0; i < 8; i++) {
                float4 qv = q4[(r0 + i) * 17 + d4];
                #pragma unroll
                for (int j = 0; j < 4; j++)
                    acc[i][j] += qv.x * kv[j].x + qv.y * kv[j].y +
                                 qv.z * kv[j].z + qv.w * kv[j].w;
            }
        }

        int mkc[4];
        #pragma unroll
        for (int j = 0; j < 4; j++) mkc[j] = mk[c0 + j];

        // ---- unnormalized E = exp(s); masked->0; fully-masked q-row->1 ----
        #pragma unroll
        for (int i = 0; i < 8; i++) {
            float4 ev;
            float* e = (float*)&ev;
            #pragma unroll
            for (int j = 0; j < 4; j++)
                e[j] = mqr[i] ? (mkc[j] ? __expf(acc[i][j] * 0.125f) : 0.f) : 1.f;
            l_i[i] += e[0] + e[1] + e[2] + e[3];
            ((float4*)Ps)[(r0 + i) * 17 + tc] = ev;
            *(float4*)(P + ((size_t)bh * Sc + (size_t)(q0 + r0 + i)) * Sc + kt + c0) = ev;
        }
        __syncthreads();

        // ---- E(tile) @ V(tile): oacc[8][4], d-cols = tc*4 ----
        #pragma unroll 8
        for (int c = 0; c < TK; c++) {
            float4 vv = v4[c * 17 + tc];
            #pragma unroll
            for (int i = 0; i < 8; i++) {
                float pr = Ps[(r0 + i) * QST + c];
                oacc[i][0] += pr * vv.x;
                oacc[i][1] += pr * vv.y;
                oacc[i][2] += pr * vv.z;
                oacc[i][3] += pr * vv.w;
            }
        }
        __syncthreads();
    }

    // ---- reduce row sums across the 16 lanes of a row group ----
    #pragma unroll
    for (int off = 1; off < 16; off <<= 1)
        #pragma unroll
        for (int i = 0; i < 8; i++)
            l_i[i] += __shfl_xor_sync(0xffffffffu, l_i[i], off, 16);

    float linv[8];
    #pragma unroll
    for (int i = 0; i < 8; i++) linv[i] = 1.f / l_i[i];

    // ---- write normalized O; stash 1/l for the P pass ----
    #pragma unroll
    for (int i = 0; i < 8; i++) {
        float4 o = make_float4(oacc[i][0] * linv[i], oacc[i][1] * linv[i],
                               oacc[i][2] * linv[i], oacc[i][3] * linv[i]);
        *(float4*)(Out + ((size_t)bh * Sc + (size_t)(q0 + r0 + i)) * Dc + c0) = o;
    }
    if (tc == 0) {
        #pragma unroll
        for (int i = 0; i < 8; i++)
            g_linv[bh * Sc + q0 + r0 + i] = linv[i];
    }
}

// rescale P rows by 1/l  (201M elems = 50.3M float4, 512 float4 per row)
__global__ __launch_bounds__(256)
void norm_p_kernel(float4* __restrict__ P4)
{
    int idx = blockIdx.x * 256 + threadIdx.x;
    int row = idx >> 9;
    float s = g_linv[row];
    float4 v = P4[idx];
    v.x *= s; v.y *= s; v.z *= s; v.w *= s;
    P4[idx] = v;
}

extern "C" void kernel_launch(void* const* d_in, const int* in_sizes, int n_in,
                              void* d_out, int out_size)
{
    const float* Q    = (const float*)d_in[0];
    const float* K    = (const float*)d_in[1];
    const float* V    = (const float*)d_in[2];
    const int*   mask = (const int*)d_in[3];
    float* out = (float*)d_out;
    float* P   = out + (size_t)Bc * Hc * Sc * Dc;

    cudaFuncSetAttribute(attn_main_kernel,
                         cudaFuncAttributeMaxDynamicSharedMemorySize, SMEM_BYTES);

    dim3 grid(Sc / TQ, Bc * Hc);
    attn_main_kernel<<<grid, NT, SMEM_BYTES>>>(Q, K, V, mask, out, P);

    int n4 = (Bc * Hc * Sc) * (Sc / 4);       // 50,331,648 float4
    norm_p_kernel<<<n4 / 256, 256>>>((float4*)P);
}